// round 12
// baseline (speedup 1.0000x reference)
#include <cuda_runtime.h>
#include <cuda_bf16.h>
#include <math.h>

#define TT 20
#define MM 2000
#define NROWS (TT*MM)          // 40000, row index = t*MM + m
#define NCHUNK 4
#define JCH (MM/NCHUNK)        // 500
#define SEG 24                 // per-chunk neighbor capacity
#define CAP (NCHUNK*SEG)       // 96

#define FMA2(d,a,b) asm("fma.rn.f32x2 %0,%1,%2,%0;" : "+l"(d) : "l"(a), "l"(b))
#define UNPK(lo,hi,v) asm("mov.b64 {%0,%1},%2;" : "=f"(lo), "=f"(hi) : "l"(v))

// ---------------- static scratch ----------------
__device__ float          d_maskf[NROWS];
__device__ int            d_cnt4[NCHUNK*NROWS];
__device__ int            d_deg[NROWS];      // zero-init; self-resetting
__device__ int            d_tick[NROWS];     // zero-init; self-resetting
__device__ float          d_dinv[NROWS];
__device__ unsigned short d_nbr[(size_t)NROWS * CAP];
__device__ float          d_bufA[(size_t)NROWS * 128];   // Z2
__device__ float          d_bufB[(size_t)NROWS * 128];   // h1 / placeholder
__device__ float          d_gpre[(size_t)NROWS * 512];   // [m*T+t][512]
__device__ float          d_lstm[(size_t)NROWS * 128];   // [m*T+t][128]

// fast nonlinearities: MUFU EX2 based, err ~1e-7 (vs 1e-3 tolerance)
__device__ __forceinline__ float sigm_f(float x) {
    return __fdividef(1.0f, 1.0f + __expf(-x));
}
__device__ __forceinline__ float tanh_f(float x) {
    return __fdividef(2.0f, 1.0f + __expf(-2.0f * x)) - 1.0f;
}

// expand packed bf16x2 (lo=k_even, hi=k_odd) to packed f32x2: 2 ALU + reg-pair mov
__device__ __forceinline__ unsigned long long bf2f2(unsigned w) {
    unsigned lo = w << 16;
    unsigned hi = w & 0xFFFF0000u;
    unsigned long long r;
    asm("mov.b64 %0, {%1, %2};" : "=l"(r) : "r"(lo), "r"(hi));
    return r;
}

// ---------------- chunked extraction + fused degree/dinv (atomic ticket) ----------------
__global__ void k_extract(const float* __restrict__ adj, const unsigned int* __restrict__ em) {
    int t = blockIdx.y;
    int ch = blockIdx.z;
    int j0 = ch * JCH;
    int i = blockIdx.x * 256 + threadIdx.x;
    __shared__ float msm[JCH];
    for (int j = threadIdx.x; j < JCH; j += 256) {
        int gj = j0 + j;
        int b = gj / 500, n = gj % 500;
        msm[j] = em[(b * TT + t) * 500 + n] ? 1.0f : 0.0f;
    }
    __syncthreads();
    if (i >= MM) return;
    const float* a = adj + (size_t)t * MM * MM + (size_t)j0 * MM + i;   // column i, chunk rows
    int idx = t * MM + i;
    unsigned short* list = d_nbr + (size_t)idx * CAP + ch * SEG;
    int cnt = 0;
    #pragma unroll 8
    for (int j = 0; j < JCH; j++) {
        float av = a[(size_t)j * MM];
        if (av != 0.0f && msm[j] != 0.0f) {
            if (cnt < SEG) list[cnt] = (unsigned short)(j0 + j);
            cnt++;
        }
    }
    int cc = (cnt < SEG ? cnt : SEG);
    d_cnt4[ch * NROWS + idx] = cc;
    atomicAdd(&d_deg[idx], cc);
    __threadfence();
    int done = atomicAdd(&d_tick[idx], 1);
    if (done == NCHUNK - 1) {            // last chunk for this column: finalize
        int tot = atomicAdd(&d_deg[idx], 0);
        int b = i / 500, n = i % 500;
        float mi = em[(b * TT + t) * 500 + n] ? 1.0f : 0.0f;
        d_maskf[idx] = mi;
        d_dinv[idx] = (mi != 0.0f) ? rsqrtf((float)tot + 1.0f) : 0.0f;
        d_deg[idx] = 0;                  // self-reset for next graph replay
        d_tick[idx] = 0;
    }
}

// ---------------- fused GCN1: h1 = relu( dinv_i * ((Σ dinv_j x_j) @ W1) + b1 ) ----------------
__global__ void k_agg1(const float2* __restrict__ pos2, const float* __restrict__ W1,
                       const float* __restrict__ b1, float* __restrict__ out) {
    int row = blockIdx.x;
    int f = threadIdx.x;
    int t = row / MM;
    size_t base = (size_t)t * MM;
    float di = d_dinv[row];
    float2 xi = __ldg(&pos2[row]);
    float wx0 = di * xi.x, wx1 = di * xi.y;      // self term
    const unsigned short* lrow = &d_nbr[(size_t)row * CAP];
    #pragma unroll
    for (int ch = 0; ch < NCHUNK; ch++) {
        int n = d_cnt4[ch * NROWS + row];
        const unsigned short* lst = lrow + ch * SEG;
        for (int idx = 0; idx < n; idx++) {
            size_t j = base + lst[idx];
            float dj = __ldg(&d_dinv[j]);
            float2 xj = __ldg(&pos2[j]);
            wx0 += dj * xj.x;
            wx1 += dj * xj.y;
        }
    }
    float v = di * (wx0 * __ldg(&W1[f]) + wx1 * __ldg(&W1[128 + f])) + __ldg(&b1[f]);
    out[(size_t)row * 128 + f] = fmaxf(v, 0.0f);
}

// ---------------- GCN2 aggregation: out = (dinv_i*(Σ Z2[j] + Z2[i]) + b2) * mask ----------------
__global__ void k_agg2(const float* __restrict__ Zin, const float* __restrict__ bias,
                       float* __restrict__ out) {
    int row = blockIdx.x;
    int f = threadIdx.x;
    int t = row / MM;
    size_t base = (size_t)t * MM;
    float acc = Zin[(size_t)row * 128 + f];
    const unsigned short* lrow = &d_nbr[(size_t)row * CAP];
    #pragma unroll
    for (int ch = 0; ch < NCHUNK; ch++) {
        int n = d_cnt4[ch * NROWS + row];
        const unsigned short* lst = lrow + ch * SEG;
        for (int idx = 0; idx < n; idx++) {
            int j = lst[idx];
            acc += Zin[(base + j) * 128 + f];
        }
    }
    float v = d_dinv[row] * acc + __ldg(&bias[f]);
    out[(size_t)row * 128 + f] = v * d_maskf[row];
}

// ---------------- tiled GEMM, K=128 fixed, packed f32x2 ----------------
// mode 0 (Z2):    A row = r,                B = W2   [k][c],  epi: *dinv[r]
// mode 1 (gates): A row = (r%20)*2000+r/20, B = W_ih [c][k],  epi: + b_ih[c]+b_hh[c]
__global__ void __launch_bounds__(256)
k_gemm(const float* __restrict__ A, const float* __restrict__ B, float* __restrict__ C,
       const float* __restrict__ bia, const float* __restrict__ bib,
       int mode, int ncols) {
    extern __shared__ float sm[];
    float* As = sm;            // [64][128]
    float* Bs = sm + 64 * 128; // [128][130]
    int r0 = blockIdx.x * 64, c0 = blockIdx.y * 128;
    int tid = threadIdx.x;

    for (int i = tid; i < 64 * 32; i += 256) {
        int row = i / 32, k4 = i % 32;
        int gr = r0 + row;
        int arow = (mode == 1) ? ((gr % TT) * MM + gr / TT) : gr;
        ((float4*)As)[row * 32 + k4] = ((const float4*)A)[(size_t)arow * 32 + k4];
    }
    if (mode == 1) {
        for (int i = tid; i < 128 * 32; i += 256) {
            int c = i / 32, k4 = i % 32;
            float4 v = ((const float4*)B)[(size_t)(c0 + c) * 32 + k4];
            Bs[c * 130 + 4 * k4 + 0] = v.x; Bs[c * 130 + 4 * k4 + 1] = v.y;
            Bs[c * 130 + 4 * k4 + 2] = v.z; Bs[c * 130 + 4 * k4 + 3] = v.w;
        }
    } else {
        for (int i = tid; i < 128 * 32; i += 256) {
            int k = i / 32, c4 = i % 32;
            float4 v = ((const float4*)B)[(size_t)k * 32 + c4];
            Bs[(4 * c4 + 0) * 130 + k] = v.x; Bs[(4 * c4 + 1) * 130 + k] = v.y;
            Bs[(4 * c4 + 2) * 130 + k] = v.z; Bs[(4 * c4 + 3) * 130 + k] = v.w;
        }
    }
    __syncthreads();

    int tx = tid % 32, ty = tid / 32;
    unsigned long long acc[8][4];
    #pragma unroll
    for (int rr = 0; rr < 8; rr++)
        #pragma unroll
        for (int cc = 0; cc < 4; cc++) acc[rr][cc] = 0ull;

    const ulonglong2* As2 = (const ulonglong2*)As;
    #pragma unroll 4
    for (int k4 = 0; k4 < 32; k4++) {
        ulonglong2 a[8];
        #pragma unroll
        for (int rr = 0; rr < 8; rr++) a[rr] = As2[(ty * 8 + rr) * 32 + k4];
        #pragma unroll
        for (int cc = 0; cc < 4; cc++) {
            int c = tx + 32 * cc;
            const unsigned long long* bp = (const unsigned long long*)(Bs + c * 130 + 4 * k4);
            unsigned long long b0 = bp[0], b1 = bp[1];
            #pragma unroll
            for (int rr = 0; rr < 8; rr++) {
                FMA2(acc[rr][cc], a[rr].x, b0);
                FMA2(acc[rr][cc], a[rr].y, b1);
            }
        }
    }
    #pragma unroll
    for (int cc = 0; cc < 4; cc++) {
        int c = tx + 32 * cc;
        float bv = (mode == 1) ? (__ldg(&bia[c0 + c]) + __ldg(&bib[c0 + c])) : 0.0f;
        #pragma unroll
        for (int rr = 0; rr < 8; rr++) {
            int r = r0 + ty * 8 + rr;
            float lo, hi; UNPK(lo, hi, acc[rr][cc]);
            float v = lo + hi;
            if (mode == 1) v += bv;
            else           v *= d_dinv[r];
            C[(size_t)r * ncols + c0 + c] = v;
        }
    }
}

// ---------------- persistent LSTM: 20 blocks, 512 threads, all weights in registers ----------------
// Thread g -> gate row grow=q*128+j. Weights k[0:64) as 32 ull fp32 regs (64 regs);
// k[64:128) as 32 u32 bf16x2 regs (32 regs) -> 96 weight regs, SAME pressure as the
// proven R10 layout, but zero weight smem traffic: crossbar/step = 512 wf (h only).
// Shuffle gate exchange, double-buffered h, one barrier/step.
__global__ void __launch_bounds__(512, 1)
k_lstm(const float* __restrict__ Whh) {
    __shared__ float hsm[256];              // [2][128] double-buffered h
    int t = blockIdx.x, g = threadIdx.x;
    int q = g & 3, j = g >> 2;
    int grow = q * 128 + j;                 // gate row in [512]

    unsigned long long w[32];               // fp32 pairs, k = 0..63
    const unsigned long long* wrow = (const unsigned long long*)(Whh + (size_t)grow * 128);
    #pragma unroll
    for (int i = 0; i < 32; i++) w[i] = wrow[i];
    unsigned wb[32];                        // bf16x2, k = 64..127
    #pragma unroll
    for (int i = 0; i < 32; i++) {
        float2 wp = *(const float2*)(Whh + (size_t)grow * 128 + 64 + 2 * i);
        __nv_bfloat162 b2 = __float22bfloat162_rn(wp);
        wb[i] = *(unsigned*)&b2;            // low 16 = k even, high 16 = k odd
    }

    float c = 0.0f;
    if (g < 128) hsm[g] = 0.0f;             // buffer 0
    __syncthreads();

    float nextg = d_gpre[(size_t)t * 512 + grow];   // m = 0
    for (int m = 0; m < MM; m++) {
        float gp = nextg;
        if (m < MM - 1) nextg = d_gpre[(size_t)((m + 1) * TT + t) * 512 + grow];
        const ulonglong2* h2 = (const ulonglong2*)(hsm + (m & 1) * 128);
        unsigned long long accA = 0ull, accB = 0ull;
        #pragma unroll
        for (int jj = 0; jj < 16; jj++) {   // k = 0..63, fp32 register weights
            ulonglong2 hv = h2[jj];
            FMA2(accA, hv.x, w[2 * jj]);
            FMA2(accB, hv.y, w[2 * jj + 1]);
        }
        #pragma unroll
        for (int i = 0; i < 16; i++) {      // k = 64..127, bf16 register weights
            ulonglong2 hv = h2[16 + i];
            FMA2(accA, hv.x, bf2f2(wb[2 * i]));
            FMA2(accB, hv.y, bf2f2(wb[2 * i + 1]));
        }
        float loA, hiA, loB, hiB;
        UNPK(loA, hiA, accA); UNPK(loB, hiB, accB);
        float part = (loA + hiA) + (loB + hiB) + gp;
        // branchless nonlinearity: tanh(x) = 2*sigm(2x)-1
        float xin = (q == 2) ? 2.0f * part : part;
        float s = sigm_f(xin);
        float act = (q == 2) ? fmaf(2.0f, s, -1.0f) : s;
        // gate exchange within warp: lanes q=0 gather f,g,o from lanes +1,+2,+3
        float a1 = __shfl_down_sync(0xffffffffu, act, 1);
        float a2 = __shfl_down_sync(0xffffffffu, act, 2);
        float a3 = __shfl_down_sync(0xffffffffu, act, 3);
        if (q == 0) {
            c = a1 * c + act * a2;                // f*c + i*g
            float hn = a3 * tanh_f(c);            // o*tanh(c)
            hsm[((m & 1) ^ 1) * 128 + j] = hn;    // write buffer
            d_lstm[(size_t)(m * TT + t) * 128 + j] = hn;
        }
        __syncthreads();
    }
}

// ---------------- fused FC1(relu)+FC2, 64 rows/block, packed f32x2 ----------------
__global__ void __launch_bounds__(256)
k_fc(const float* __restrict__ fc1w, const float* __restrict__ fc1b,
     const float* __restrict__ fc2w, const float* __restrict__ fc2b,
     float* __restrict__ out) {
    extern __shared__ float sm[];
    float* w1t = sm;                   // [64][130]
    float* w2t = w1t + 64 * 130;       // [32][66]
    float* xs  = w2t + 32 * 66;        // [64][128]
    float* mid = xs  + 64 * 128;       // [64][66]
    int tid = threadIdx.x;

    for (int i = tid; i < 128 * 64; i += 256) {
        int k = i >> 6, cc = i & 63;
        w1t[cc * 130 + k] = fc1w[i];
    }
    for (int i = tid; i < 64 * 32; i += 256) {
        int k = i >> 5, o = i & 31;
        w2t[o * 66 + k] = fc2w[i];
    }
    int rbase = blockIdx.x * 64;
    for (int i = tid; i < 64 * 32; i += 256)
        ((float4*)xs)[i] = ((const float4*)d_lstm)[(size_t)rbase * 32 + i];
    __syncthreads();

    int r = tid >> 2, q = tid & 3;
    {
        unsigned long long acc[16];
        #pragma unroll
        for (int j = 0; j < 16; j++) acc[j] = 0ull;
        const unsigned long long* xr = (const unsigned long long*)(xs + r * 128);
        #pragma unroll 4
        for (int kp = 0; kp < 64; kp++) {
            unsigned long long xv = xr[kp];
            #pragma unroll
            for (int j = 0; j < 16; j++)
                FMA2(acc[j], xv, *(const unsigned long long*)(w1t + (q * 16 + j) * 130 + 2 * kp));
        }
        #pragma unroll
        for (int j = 0; j < 16; j++) {
            float lo, hi; UNPK(lo, hi, acc[j]);
            int cc = q * 16 + j;
            mid[r * 66 + cc] = fmaxf(lo + hi + __ldg(&fc1b[cc]), 0.0f);
        }
    }
    __syncthreads();
    {
        unsigned long long acc[8];
        #pragma unroll
        for (int j = 0; j < 8; j++) acc[j] = 0ull;
        const unsigned long long* mr = (const unsigned long long*)(mid + r * 66);
        #pragma unroll 4
        for (int kp = 0; kp < 32; kp++) {
            unsigned long long mv = mr[kp];
            #pragma unroll
            for (int j = 0; j < 8; j++)
                FMA2(acc[j], mv, *(const unsigned long long*)(w2t + (q * 8 + j) * 66 + 2 * kp));
        }
        #pragma unroll
        for (int j = 0; j < 8; j++) {
            float lo, hi; UNPK(lo, hi, acc[j]);
            int o = q * 8 + j;
            out[(size_t)(rbase + r) * 32 + o] = lo + hi + __ldg(&fc2b[o]);
        }
    }
}

// ---------------- launch ----------------
extern "C" void kernel_launch(void* const* d_in, const int* in_sizes, int n_in,
                              void* d_out, int out_size) {
    const float* positions = (const float*)d_in[0];
    const float* adjacency = (const float*)d_in[1];
    const unsigned int* ego = (const unsigned int*)d_in[2];
    const float* W1   = (const float*)d_in[3];
    const float* b1   = (const float*)d_in[4];
    const float* W2   = (const float*)d_in[5];
    const float* b2   = (const float*)d_in[6];
    const float* W_ih = (const float*)d_in[7];
    const float* W_hh = (const float*)d_in[8];
    const float* b_ih = (const float*)d_in[9];
    const float* b_hh = (const float*)d_in[10];
    const float* fc1w = (const float*)d_in[11];
    const float* fc1b = (const float*)d_in[12];
    const float* fc2w = (const float*)d_in[13];
    const float* fc2b = (const float*)d_in[14];
    float* out = (float*)d_out;

    static const int GEMM_SMEM = (64 * 128 + 128 * 130) * 4;            // 99328
    static const int FC_SMEM   = (64 * 130 + 32 * 66 + 64 * 128 + 64 * 66) * 4;  // 91392
    cudaFuncSetAttribute(k_gemm, cudaFuncAttributeMaxDynamicSharedMemorySize, GEMM_SMEM);
    cudaFuncSetAttribute(k_fc,   cudaFuncAttributeMaxDynamicSharedMemorySize, FC_SMEM);

    float* bufA; cudaGetSymbolAddress((void**)&bufA, d_bufA);
    float* bufB; cudaGetSymbolAddress((void**)&bufB, d_bufB);
    float* gpre; cudaGetSymbolAddress((void**)&gpre, d_gpre);

    k_extract<<<dim3(8, TT, NCHUNK), 256>>>(adjacency, ego);
    k_agg1<<<NROWS, 128>>>((const float2*)positions, W1, b1, bufB);
    k_gemm<<<dim3(625, 1), 256, GEMM_SMEM>>>(bufB, W2, bufA, 0, 0, 0, 128);
    k_agg2<<<NROWS, 128>>>(bufA, b2, bufB);
    k_gemm<<<dim3(625, 4), 256, GEMM_SMEM>>>(bufB, W_ih, gpre, b_ih, b_hh, 1, 512);
    k_lstm<<<TT, 512>>>(W_hh);
    k_fc<<<625, 256, FC_SMEM>>>(fc1w, fc1b, fc2w, fc2b, out);
}

// round 13
// speedup vs baseline: 1.9712x; 1.9712x over previous
#include <cuda_runtime.h>
#include <cuda_bf16.h>
#include <cuda_fp16.h>
#include <math.h>

#define TT 20
#define MM 2000
#define NROWS (TT*MM)          // 40000, row index = t*MM + m
#define NCHUNK 4
#define JCH (MM/NCHUNK)        // 500
#define SEG 24                 // per-chunk neighbor capacity
#define CAP (NCHUNK*SEG)       // 96

#define FMA2(d,a,b) asm("fma.rn.f32x2 %0,%1,%2,%0;" : "+l"(d) : "l"(a), "l"(b))
#define UNPK(lo,hi,v) asm("mov.b64 {%0,%1},%2;" : "=f"(lo), "=f"(hi) : "l"(v))

// ---------------- static scratch ----------------
__device__ float          d_maskf[NROWS];
__device__ int            d_cnt4[NCHUNK*NROWS];
__device__ int            d_deg[NROWS];      // zero-init; self-resetting
__device__ int            d_tick[NROWS];     // zero-init; self-resetting
__device__ float          d_dinv[NROWS];
__device__ unsigned short d_nbr[(size_t)NROWS * CAP];
__device__ float          d_bufA[(size_t)NROWS * 128];   // Z2
__device__ float          d_bufB[(size_t)NROWS * 128];   // h1 / placeholder
__device__ float          d_gpre[(size_t)NROWS * 512];   // [m*T+t][512]
__device__ float          d_lstm[(size_t)NROWS * 128];   // [m*T+t][128]

// fast nonlinearities: MUFU EX2 based, err ~1e-7 (vs 1e-3 tolerance)
__device__ __forceinline__ float sigm_f(float x) {
    return __fdividef(1.0f, 1.0f + __expf(-x));
}
__device__ __forceinline__ float tanh_f(float x) {
    return __fdividef(2.0f, 1.0f + __expf(-2.0f * x)) - 1.0f;
}

// ---------------- chunked extraction + fused degree/dinv (atomic ticket) ----------------
__global__ void k_extract(const float* __restrict__ adj, const unsigned int* __restrict__ em) {
    int t = blockIdx.y;
    int ch = blockIdx.z;
    int j0 = ch * JCH;
    int i = blockIdx.x * 256 + threadIdx.x;
    __shared__ float msm[JCH];
    for (int j = threadIdx.x; j < JCH; j += 256) {
        int gj = j0 + j;
        int b = gj / 500, n = gj % 500;
        msm[j] = em[(b * TT + t) * 500 + n] ? 1.0f : 0.0f;
    }
    __syncthreads();
    if (i >= MM) return;
    const float* a = adj + (size_t)t * MM * MM + (size_t)j0 * MM + i;   // column i, chunk rows
    int idx = t * MM + i;
    unsigned short* list = d_nbr + (size_t)idx * CAP + ch * SEG;
    int cnt = 0;
    #pragma unroll 8
    for (int j = 0; j < JCH; j++) {
        float av = a[(size_t)j * MM];
        if (av != 0.0f && msm[j] != 0.0f) {
            if (cnt < SEG) list[cnt] = (unsigned short)(j0 + j);
            cnt++;
        }
    }
    int cc = (cnt < SEG ? cnt : SEG);
    d_cnt4[ch * NROWS + idx] = cc;
    atomicAdd(&d_deg[idx], cc);
    __threadfence();
    int done = atomicAdd(&d_tick[idx], 1);
    if (done == NCHUNK - 1) {            // last chunk for this column: finalize
        int tot = atomicAdd(&d_deg[idx], 0);
        int b = i / 500, n = i % 500;
        float mi = em[(b * TT + t) * 500 + n] ? 1.0f : 0.0f;
        d_maskf[idx] = mi;
        d_dinv[idx] = (mi != 0.0f) ? rsqrtf((float)tot + 1.0f) : 0.0f;
        d_deg[idx] = 0;                  // self-reset for next graph replay
        d_tick[idx] = 0;
    }
}

// ---------------- fused GCN1: h1 = relu( dinv_i * ((Σ dinv_j x_j) @ W1) + b1 ) ----------------
__global__ void k_agg1(const float2* __restrict__ pos2, const float* __restrict__ W1,
                       const float* __restrict__ b1, float* __restrict__ out) {
    int row = blockIdx.x;
    int f = threadIdx.x;
    int t = row / MM;
    size_t base = (size_t)t * MM;
    float di = d_dinv[row];
    float2 xi = __ldg(&pos2[row]);
    float wx0 = di * xi.x, wx1 = di * xi.y;      // self term
    const unsigned short* lrow = &d_nbr[(size_t)row * CAP];
    #pragma unroll
    for (int ch = 0; ch < NCHUNK; ch++) {
        int n = d_cnt4[ch * NROWS + row];
        const unsigned short* lst = lrow + ch * SEG;
        for (int idx = 0; idx < n; idx++) {
            size_t j = base + lst[idx];
            float dj = __ldg(&d_dinv[j]);
            float2 xj = __ldg(&pos2[j]);
            wx0 += dj * xj.x;
            wx1 += dj * xj.y;
        }
    }
    float v = di * (wx0 * __ldg(&W1[f]) + wx1 * __ldg(&W1[128 + f])) + __ldg(&b1[f]);
    out[(size_t)row * 128 + f] = fmaxf(v, 0.0f);
}

// ---------------- GCN2 aggregation: out = (dinv_i*(Σ Z2[j] + Z2[i]) + b2) * mask ----------------
__global__ void k_agg2(const float* __restrict__ Zin, const float* __restrict__ bias,
                       float* __restrict__ out) {
    int row = blockIdx.x;
    int f = threadIdx.x;
    int t = row / MM;
    size_t base = (size_t)t * MM;
    float acc = Zin[(size_t)row * 128 + f];
    const unsigned short* lrow = &d_nbr[(size_t)row * CAP];
    #pragma unroll
    for (int ch = 0; ch < NCHUNK; ch++) {
        int n = d_cnt4[ch * NROWS + row];
        const unsigned short* lst = lrow + ch * SEG;
        for (int idx = 0; idx < n; idx++) {
            int j = lst[idx];
            acc += Zin[(base + j) * 128 + f];
        }
    }
    float v = d_dinv[row] * acc + __ldg(&bias[f]);
    out[(size_t)row * 128 + f] = v * d_maskf[row];
}

// ---------------- tiled GEMM, K=128 fixed, 64-col blocks, packed f32x2 ----------------
// mode 0 (Z2):    A row = r,                B = W2   [k][c],  epi: *dinv[r]
// mode 1 (gates): A row = (r%20)*2000+r/20, B = W_ih [c][k],  epi: + b_ih[c]+b_hh[c]
__global__ void __launch_bounds__(256)
k_gemm(const float* __restrict__ A, const float* __restrict__ B, float* __restrict__ C,
       const float* __restrict__ bia, const float* __restrict__ bib,
       int mode, int ncols) {
    extern __shared__ float sm[];
    float* As = sm;            // [64][128]
    float* Bs = sm + 64 * 128; // [64][130]
    int r0 = blockIdx.x * 64, c0 = blockIdx.y * 64;
    int tid = threadIdx.x;

    for (int i = tid; i < 64 * 32; i += 256) {
        int row = i / 32, k4 = i % 32;
        int gr = r0 + row;
        int arow = (mode == 1) ? ((gr % TT) * MM + gr / TT) : gr;
        ((float4*)As)[row * 32 + k4] = ((const float4*)A)[(size_t)arow * 32 + k4];
    }
    if (mode == 1) {  // B = W_ih [c][k]: rows c0..c0+63
        for (int i = tid; i < 64 * 32; i += 256) {
            int c = i / 32, k4 = i % 32;
            float4 v = ((const float4*)B)[(size_t)(c0 + c) * 32 + k4];
            Bs[c * 130 + 4 * k4 + 0] = v.x; Bs[c * 130 + 4 * k4 + 1] = v.y;
            Bs[c * 130 + 4 * k4 + 2] = v.z; Bs[c * 130 + 4 * k4 + 3] = v.w;
        }
    } else {          // B = W2 [k][c]: transpose cols c0..c0+63 into Bs[c][k]
        for (int i = tid; i < 128 * 16; i += 256) {
            int k = i / 16, c4 = i % 16;
            float4 v = ((const float4*)B)[(size_t)k * 32 + (c0 >> 2) + c4];
            Bs[(4 * c4 + 0) * 130 + k] = v.x; Bs[(4 * c4 + 1) * 130 + k] = v.y;
            Bs[(4 * c4 + 2) * 130 + k] = v.z; Bs[(4 * c4 + 3) * 130 + k] = v.w;
        }
    }
    __syncthreads();

    int tx = tid % 32, ty = tid / 32;
    unsigned long long acc[8][2];
    #pragma unroll
    for (int rr = 0; rr < 8; rr++)
        #pragma unroll
        for (int cc = 0; cc < 2; cc++) acc[rr][cc] = 0ull;

    const ulonglong2* As2 = (const ulonglong2*)As;
    #pragma unroll 4
    for (int k4 = 0; k4 < 32; k4++) {
        ulonglong2 a[8];
        #pragma unroll
        for (int rr = 0; rr < 8; rr++) a[rr] = As2[(ty * 8 + rr) * 32 + k4];
        #pragma unroll
        for (int cc = 0; cc < 2; cc++) {
            int c = tx + 32 * cc;
            const unsigned long long* bp = (const unsigned long long*)(Bs + c * 130 + 4 * k4);
            unsigned long long b0 = bp[0], b1 = bp[1];
            #pragma unroll
            for (int rr = 0; rr < 8; rr++) {
                FMA2(acc[rr][cc], a[rr].x, b0);
                FMA2(acc[rr][cc], a[rr].y, b1);
            }
        }
    }
    #pragma unroll
    for (int cc = 0; cc < 2; cc++) {
        int c = tx + 32 * cc;
        float bv = (mode == 1) ? (__ldg(&bia[c0 + c]) + __ldg(&bib[c0 + c])) : 0.0f;
        #pragma unroll
        for (int rr = 0; rr < 8; rr++) {
            int r = r0 + ty * 8 + rr;
            float lo, hi; UNPK(lo, hi, acc[rr][cc]);
            float v = lo + hi;
            if (mode == 1) v += bv;
            else           v *= d_dinv[r];
            C[(size_t)r * ncols + c0 + c] = v;
        }
    }
}

// ---------------- persistent LSTM: 20 blocks, 512 threads, fp16 HFMA2 dot ----------------
// Thread g -> gate row grow=q*128+j. ALL 128 weights in 64 half2 regs (fp16);
// h stored in smem as half2 (writer converts), double-buffered. Dot = 64 HFMA2
// over 4 independent chains, combined in fp32. c, h outputs, gpre stay fp32, so
// quantization does not recur through the state. Shuffle gate exchange, 1 bar/step.
__global__ void __launch_bounds__(512, 1)
k_lstm(const float* __restrict__ Whh) {
    __shared__ __align__(16) unsigned hb[128];   // [2][64] u32 = half2 h, double-buffered
    int t = blockIdx.x, g = threadIdx.x;
    int q = g & 3, j = g >> 2;
    int grow = q * 128 + j;                      // gate row in [512]

    __half2 wh[64];
    const float2* wrow = (const float2*)(Whh + (size_t)grow * 128);
    #pragma unroll
    for (int i = 0; i < 64; i++) wh[i] = __float22half2_rn(wrow[i]);

    float c = 0.0f;
    if (g < 128) hb[g] = 0u;                     // zero both buffers
    __syncthreads();

    float nextg = d_gpre[(size_t)t * 512 + grow];   // m = 0
    for (int m = 0; m < MM; m++) {
        float gp = nextg;
        if (m < MM - 1) nextg = d_gpre[(size_t)((m + 1) * TT + t) * 512 + grow];
        const uint4* h4 = (const uint4*)(hb + (m & 1) * 64);
        __half2 a0 = __float2half2_rn(0.0f), a1 = a0, a2 = a0, a3 = a0;
        #pragma unroll
        for (int i = 0; i < 16; i++) {           // 64 HFMA2 over 4 chains
            uint4 hv = h4[i];
            a0 = __hfma2(*(__half2*)&hv.x, wh[4 * i + 0], a0);
            a1 = __hfma2(*(__half2*)&hv.y, wh[4 * i + 1], a1);
            a2 = __hfma2(*(__half2*)&hv.z, wh[4 * i + 2], a2);
            a3 = __hfma2(*(__half2*)&hv.w, wh[4 * i + 3], a3);
        }
        float part = (__low2float(a0) + __high2float(a0))
                   + (__low2float(a1) + __high2float(a1))
                   + (__low2float(a2) + __high2float(a2))
                   + (__low2float(a3) + __high2float(a3)) + gp;
        // branchless nonlinearity: tanh(x) = 2*sigm(2x)-1
        float xin = (q == 2) ? 2.0f * part : part;
        float s = sigm_f(xin);
        float act = (q == 2) ? fmaf(2.0f, s, -1.0f) : s;
        // gate exchange within warp: lanes q=0 gather f,g,o from lanes +1,+2,+3
        float af = __shfl_down_sync(0xffffffffu, act, 1);
        float ag = __shfl_down_sync(0xffffffffu, act, 2);
        float ao = __shfl_down_sync(0xffffffffu, act, 3);
        if (q == 0) {
            c = af * c + act * ag;               // f*c + i*g
            float hn = ao * tanh_f(c);           // o*tanh(c)
            __half* wbuf = (__half*)(hb + ((m & 1) ^ 1) * 64);
            wbuf[j] = __float2half_rn(hn);       // write buffer (fp16 for next dot)
            d_lstm[(size_t)(m * TT + t) * 128 + j] = hn;
        }
        __syncthreads();
    }
}

// ---------------- fused FC1(relu)+FC2, 64 rows/block, packed f32x2 ----------------
__global__ void __launch_bounds__(256)
k_fc(const float* __restrict__ fc1w, const float* __restrict__ fc1b,
     const float* __restrict__ fc2w, const float* __restrict__ fc2b,
     float* __restrict__ out) {
    extern __shared__ float sm[];
    float* w1t = sm;                   // [64][130]
    float* w2t = w1t + 64 * 130;       // [32][66]
    float* xs  = w2t + 32 * 66;        // [64][128]
    float* mid = xs  + 64 * 128;       // [64][66]
    int tid = threadIdx.x;

    for (int i = tid; i < 128 * 64; i += 256) {
        int k = i >> 6, cc = i & 63;
        w1t[cc * 130 + k] = fc1w[i];
    }
    for (int i = tid; i < 64 * 32; i += 256) {
        int k = i >> 5, o = i & 31;
        w2t[o * 66 + k] = fc2w[i];
    }
    int rbase = blockIdx.x * 64;
    for (int i = tid; i < 64 * 32; i += 256)
        ((float4*)xs)[i] = ((const float4*)d_lstm)[(size_t)rbase * 32 + i];
    __syncthreads();

    int r = tid >> 2, q = tid & 3;
    {
        unsigned long long acc[16];
        #pragma unroll
        for (int j = 0; j < 16; j++) acc[j] = 0ull;
        const unsigned long long* xr = (const unsigned long long*)(xs + r * 128);
        #pragma unroll 4
        for (int kp = 0; kp < 64; kp++) {
            unsigned long long xv = xr[kp];
            #pragma unroll
            for (int j = 0; j < 16; j++)
                FMA2(acc[j], xv, *(const unsigned long long*)(w1t + (q * 16 + j) * 130 + 2 * kp));
        }
        #pragma unroll
        for (int j = 0; j < 16; j++) {
            float lo, hi; UNPK(lo, hi, acc[j]);
            int cc = q * 16 + j;
            mid[r * 66 + cc] = fmaxf(lo + hi + __ldg(&fc1b[cc]), 0.0f);
        }
    }
    __syncthreads();
    {
        unsigned long long acc[8];
        #pragma unroll
        for (int j = 0; j < 8; j++) acc[j] = 0ull;
        const unsigned long long* mr = (const unsigned long long*)(mid + r * 66);
        #pragma unroll 4
        for (int kp = 0; kp < 32; kp++) {
            unsigned long long mv = mr[kp];
            #pragma unroll
            for (int j = 0; j < 8; j++)
                FMA2(acc[j], mv, *(const unsigned long long*)(w2t + (q * 8 + j) * 66 + 2 * kp));
        }
        #pragma unroll
        for (int j = 0; j < 8; j++) {
            float lo, hi; UNPK(lo, hi, acc[j]);
            int o = q * 8 + j;
            out[(size_t)(rbase + r) * 32 + o] = lo + hi + __ldg(&fc2b[o]);
        }
    }
}

// ---------------- launch ----------------
extern "C" void kernel_launch(void* const* d_in, const int* in_sizes, int n_in,
                              void* d_out, int out_size) {
    const float* positions = (const float*)d_in[0];
    const float* adjacency = (const float*)d_in[1];
    const unsigned int* ego = (const unsigned int*)d_in[2];
    const float* W1   = (const float*)d_in[3];
    const float* b1   = (const float*)d_in[4];
    const float* W2   = (const float*)d_in[5];
    const float* b2   = (const float*)d_in[6];
    const float* W_ih = (const float*)d_in[7];
    const float* W_hh = (const float*)d_in[8];
    const float* b_ih = (const float*)d_in[9];
    const float* b_hh = (const float*)d_in[10];
    const float* fc1w = (const float*)d_in[11];
    const float* fc1b = (const float*)d_in[12];
    const float* fc2w = (const float*)d_in[13];
    const float* fc2b = (const float*)d_in[14];
    float* out = (float*)d_out;

    static const int GEMM_SMEM = (64 * 128 + 64 * 130) * 4;             // 66048
    static const int FC_SMEM   = (64 * 130 + 32 * 66 + 64 * 128 + 64 * 66) * 4;  // 91392
    cudaFuncSetAttribute(k_gemm, cudaFuncAttributeMaxDynamicSharedMemorySize, GEMM_SMEM);
    cudaFuncSetAttribute(k_fc,   cudaFuncAttributeMaxDynamicSharedMemorySize, FC_SMEM);

    float* bufA; cudaGetSymbolAddress((void**)&bufA, d_bufA);
    float* bufB; cudaGetSymbolAddress((void**)&bufB, d_bufB);
    float* gpre; cudaGetSymbolAddress((void**)&gpre, d_gpre);

    k_extract<<<dim3(8, TT, NCHUNK), 256>>>(adjacency, ego);
    k_agg1<<<NROWS, 128>>>((const float2*)positions, W1, b1, bufB);
    k_gemm<<<dim3(625, 2), 256, GEMM_SMEM>>>(bufB, W2, bufA, 0, 0, 0, 128);
    k_agg2<<<NROWS, 128>>>(bufA, b2, bufB);
    k_gemm<<<dim3(625, 8), 256, GEMM_SMEM>>>(bufB, W_ih, gpre, b_ih, b_hh, 1, 512);
    k_lstm<<<TT, 512>>>(W_hh);
    k_fc<<<625, 256, FC_SMEM>>>(fc1w, fc1b, fc2w, fc2b, out);
}

// round 14
// speedup vs baseline: 2.6272x; 1.3328x over previous
#include <cuda_runtime.h>
#include <cuda_bf16.h>
#include <cuda_fp16.h>
#include <math.h>

#define TT 20
#define MM 2000
#define NROWS (TT*MM)          // 40000, row index = t*MM + m
#define NCHUNK 4
#define JCH (MM/NCHUNK)        // 500
#define SEG 24                 // per-chunk neighbor capacity
#define CAP (NCHUNK*SEG)       // 96

#define FMA2(d,a,b) asm("fma.rn.f32x2 %0,%1,%2,%0;" : "+l"(d) : "l"(a), "l"(b))
#define UNPK(lo,hi,v) asm("mov.b64 {%0,%1},%2;" : "=f"(lo), "=f"(hi) : "l"(v))

// ---------------- static scratch ----------------
__device__ float          d_maskf[NROWS];
__device__ int            d_cnt4[NCHUNK*NROWS];
__device__ int            d_deg[NROWS];      // zero-init; self-resetting
__device__ int            d_tick[NROWS];     // zero-init; self-resetting
__device__ float          d_dinv[NROWS];
__device__ unsigned short d_nbr[(size_t)NROWS * CAP];
__device__ float          d_bufA[(size_t)NROWS * 128];   // Z2
__device__ float          d_bufB[(size_t)NROWS * 128];   // h1 / placeholder
__device__ float          d_gpre[(size_t)NROWS * 512];   // [m*T+t][512]
__device__ float          d_lstm[(size_t)NROWS * 128];   // [m*T+t][128]

// fast nonlinearities: MUFU EX2 based, err ~1e-7 (vs 1e-3 tolerance)
__device__ __forceinline__ float sigm_f(float x) {
    return __fdividef(1.0f, 1.0f + __expf(-x));
}
__device__ __forceinline__ float tanh_f(float x) {
    return __fdividef(2.0f, 1.0f + __expf(-2.0f * x)) - 1.0f;
}

// ---------------- chunked extraction + fused degree/dinv (atomic ticket) ----------------
__global__ void k_extract(const float* __restrict__ adj, const unsigned int* __restrict__ em) {
    int t = blockIdx.y;
    int ch = blockIdx.z;
    int j0 = ch * JCH;
    int i = blockIdx.x * 256 + threadIdx.x;
    __shared__ float msm[JCH];
    for (int j = threadIdx.x; j < JCH; j += 256) {
        int gj = j0 + j;
        int b = gj / 500, n = gj % 500;
        msm[j] = em[(b * TT + t) * 500 + n] ? 1.0f : 0.0f;
    }
    __syncthreads();
    if (i >= MM) return;
    const float* a = adj + (size_t)t * MM * MM + (size_t)j0 * MM + i;   // column i, chunk rows
    int idx = t * MM + i;
    unsigned short* list = d_nbr + (size_t)idx * CAP + ch * SEG;
    int cnt = 0;
    #pragma unroll 8
    for (int j = 0; j < JCH; j++) {
        float av = a[(size_t)j * MM];
        if (av != 0.0f && msm[j] != 0.0f) {
            if (cnt < SEG) list[cnt] = (unsigned short)(j0 + j);
            cnt++;
        }
    }
    int cc = (cnt < SEG ? cnt : SEG);
    d_cnt4[ch * NROWS + idx] = cc;
    atomicAdd(&d_deg[idx], cc);
    __threadfence();
    int done = atomicAdd(&d_tick[idx], 1);
    if (done == NCHUNK - 1) {            // last chunk for this column: finalize
        int tot = atomicAdd(&d_deg[idx], 0);
        int b = i / 500, n = i % 500;
        float mi = em[(b * TT + t) * 500 + n] ? 1.0f : 0.0f;
        d_maskf[idx] = mi;
        d_dinv[idx] = (mi != 0.0f) ? rsqrtf((float)tot + 1.0f) : 0.0f;
        d_deg[idx] = 0;                  // self-reset for next graph replay
        d_tick[idx] = 0;
    }
}

// ---------------- fused GCN1: h1 = relu( dinv_i * ((Σ dinv_j x_j) @ W1) + b1 ) ----------------
__global__ void k_agg1(const float2* __restrict__ pos2, const float* __restrict__ W1,
                       const float* __restrict__ b1, float* __restrict__ out) {
    int row = blockIdx.x;
    int f = threadIdx.x;
    int t = row / MM;
    size_t base = (size_t)t * MM;
    float di = d_dinv[row];
    float2 xi = __ldg(&pos2[row]);
    float wx0 = di * xi.x, wx1 = di * xi.y;      // self term
    const unsigned short* lrow = &d_nbr[(size_t)row * CAP];
    #pragma unroll
    for (int ch = 0; ch < NCHUNK; ch++) {
        int n = d_cnt4[ch * NROWS + row];
        const unsigned short* lst = lrow + ch * SEG;
        for (int idx = 0; idx < n; idx++) {
            size_t j = base + lst[idx];
            float dj = __ldg(&d_dinv[j]);
            float2 xj = __ldg(&pos2[j]);
            wx0 += dj * xj.x;
            wx1 += dj * xj.y;
        }
    }
    float v = di * (wx0 * __ldg(&W1[f]) + wx1 * __ldg(&W1[128 + f])) + __ldg(&b1[f]);
    out[(size_t)row * 128 + f] = fmaxf(v, 0.0f);
}

// ---------------- GCN2 aggregation: out = (dinv_i*(Σ Z2[j] + Z2[i]) + b2) * mask ----------------
__global__ void k_agg2(const float* __restrict__ Zin, const float* __restrict__ bias,
                       float* __restrict__ out) {
    int row = blockIdx.x;
    int f = threadIdx.x;
    int t = row / MM;
    size_t base = (size_t)t * MM;
    float acc = Zin[(size_t)row * 128 + f];
    const unsigned short* lrow = &d_nbr[(size_t)row * CAP];
    #pragma unroll
    for (int ch = 0; ch < NCHUNK; ch++) {
        int n = d_cnt4[ch * NROWS + row];
        const unsigned short* lst = lrow + ch * SEG;
        for (int idx = 0; idx < n; idx++) {
            int j = lst[idx];
            acc += Zin[(base + j) * 128 + f];
        }
    }
    float v = d_dinv[row] * acc + __ldg(&bias[f]);
    out[(size_t)row * 128 + f] = v * d_maskf[row];
}

// ---------------- tiled GEMM, K=128 fixed, packed f32x2 (proven R10 BN-128 version) ----------------
// mode 0 (Z2):    A row = r,                B = W2   [k][c],  epi: *dinv[r]
// mode 1 (gates): A row = (r%20)*2000+r/20, B = W_ih [c][k],  epi: + b_ih[c]+b_hh[c]
__global__ void __launch_bounds__(256)
k_gemm(const float* __restrict__ A, const float* __restrict__ B, float* __restrict__ C,
       const float* __restrict__ bia, const float* __restrict__ bib,
       int mode, int ncols) {
    extern __shared__ float sm[];
    float* As = sm;            // [64][128]
    float* Bs = sm + 64 * 128; // [128][130]
    int r0 = blockIdx.x * 64, c0 = blockIdx.y * 128;
    int tid = threadIdx.x;

    for (int i = tid; i < 64 * 32; i += 256) {
        int row = i / 32, k4 = i % 32;
        int gr = r0 + row;
        int arow = (mode == 1) ? ((gr % TT) * MM + gr / TT) : gr;
        ((float4*)As)[row * 32 + k4] = ((const float4*)A)[(size_t)arow * 32 + k4];
    }
    if (mode == 1) {
        for (int i = tid; i < 128 * 32; i += 256) {
            int c = i / 32, k4 = i % 32;
            float4 v = ((const float4*)B)[(size_t)(c0 + c) * 32 + k4];
            Bs[c * 130 + 4 * k4 + 0] = v.x; Bs[c * 130 + 4 * k4 + 1] = v.y;
            Bs[c * 130 + 4 * k4 + 2] = v.z; Bs[c * 130 + 4 * k4 + 3] = v.w;
        }
    } else {
        for (int i = tid; i < 128 * 32; i += 256) {
            int k = i / 32, c4 = i % 32;
            float4 v = ((const float4*)B)[(size_t)k * 32 + c4];
            Bs[(4 * c4 + 0) * 130 + k] = v.x; Bs[(4 * c4 + 1) * 130 + k] = v.y;
            Bs[(4 * c4 + 2) * 130 + k] = v.z; Bs[(4 * c4 + 3) * 130 + k] = v.w;
        }
    }
    __syncthreads();

    int tx = tid % 32, ty = tid / 32;
    unsigned long long acc[8][4];
    #pragma unroll
    for (int rr = 0; rr < 8; rr++)
        #pragma unroll
        for (int cc = 0; cc < 4; cc++) acc[rr][cc] = 0ull;

    const ulonglong2* As2 = (const ulonglong2*)As;
    #pragma unroll 4
    for (int k4 = 0; k4 < 32; k4++) {
        ulonglong2 a[8];
        #pragma unroll
        for (int rr = 0; rr < 8; rr++) a[rr] = As2[(ty * 8 + rr) * 32 + k4];
        #pragma unroll
        for (int cc = 0; cc < 4; cc++) {
            int c = tx + 32 * cc;
            const unsigned long long* bp = (const unsigned long long*)(Bs + c * 130 + 4 * k4);
            unsigned long long b0 = bp[0], b1 = bp[1];
            #pragma unroll
            for (int rr = 0; rr < 8; rr++) {
                FMA2(acc[rr][cc], a[rr].x, b0);
                FMA2(acc[rr][cc], a[rr].y, b1);
            }
        }
    }
    #pragma unroll
    for (int cc = 0; cc < 4; cc++) {
        int c = tx + 32 * cc;
        float bv = (mode == 1) ? (__ldg(&bia[c0 + c]) + __ldg(&bib[c0 + c])) : 0.0f;
        #pragma unroll
        for (int rr = 0; rr < 8; rr++) {
            int r = r0 + ty * 8 + rr;
            float lo, hi; UNPK(lo, hi, acc[rr][cc]);
            float v = lo + hi;
            if (mode == 1) v += bv;
            else           v *= d_dinv[r];
            C[(size_t)r * ncols + c0 + c] = v;
        }
    }
}

// ---------------- persistent LSTM: 20 blocks, 512 threads, fp16 HFMA2 + 4-deep gpre prefetch ----------------
// Thread g -> gate row grow=q*128+j. ALL 128 weights in 64 half2 regs (fp16);
// h stored in smem as half2, double-buffered. Dot = 64 HFMA2 over 4 chains,
// combined fp32. gpre prefetched 4 steps ahead (MLP 4 -> DRAM latency covered
// by 3 full steps). c, h outputs, gpre stay fp32. Shuffle gate exchange, 1 bar/step.
__global__ void __launch_bounds__(512, 1)
k_lstm(const float* __restrict__ Whh) {
    __shared__ __align__(16) unsigned hb[128];   // [2][64] u32 = half2 h, double-buffered
    int t = blockIdx.x, g = threadIdx.x;
    int q = g & 3, j = g >> 2;
    int grow = q * 128 + j;                      // gate row in [512]

    __half2 wh[64];
    const float2* wrow = (const float2*)(Whh + (size_t)grow * 128);
    #pragma unroll
    for (int i = 0; i < 64; i++) wh[i] = __float22half2_rn(wrow[i]);

    float c = 0.0f;
    if (g < 128) hb[g] = 0u;                     // zero both buffers
    __syncthreads();

    // 4-deep gpre prefetch ring: gp0 = step m, ng1..ng3 = m+1..m+3 in flight
    float gp0 = d_gpre[(size_t)(0 * TT + t) * 512 + grow];
    float ng1 = d_gpre[(size_t)(1 * TT + t) * 512 + grow];
    float ng2 = d_gpre[(size_t)(2 * TT + t) * 512 + grow];
    float ng3 = d_gpre[(size_t)(3 * TT + t) * 512 + grow];

    for (int m = 0; m < MM; m++) {
        float gp = gp0;
        gp0 = ng1; ng1 = ng2; ng2 = ng3;
        if (m + 4 < MM) ng3 = d_gpre[(size_t)((m + 4) * TT + t) * 512 + grow];
        const uint4* h4 = (const uint4*)(hb + (m & 1) * 64);
        __half2 a0 = __float2half2_rn(0.0f), a1 = a0, a2 = a0, a3 = a0;
        #pragma unroll
        for (int i = 0; i < 16; i++) {           // 64 HFMA2 over 4 chains
            uint4 hv = h4[i];
            a0 = __hfma2(*(__half2*)&hv.x, wh[4 * i + 0], a0);
            a1 = __hfma2(*(__half2*)&hv.y, wh[4 * i + 1], a1);
            a2 = __hfma2(*(__half2*)&hv.z, wh[4 * i + 2], a2);
            a3 = __hfma2(*(__half2*)&hv.w, wh[4 * i + 3], a3);
        }
        float part = (__low2float(a0) + __high2float(a0))
                   + (__low2float(a1) + __high2float(a1))
                   + (__low2float(a2) + __high2float(a2))
                   + (__low2float(a3) + __high2float(a3)) + gp;
        // branchless nonlinearity: tanh(x) = 2*sigm(2x)-1
        float xin = (q == 2) ? 2.0f * part : part;
        float s = sigm_f(xin);
        float act = (q == 2) ? fmaf(2.0f, s, -1.0f) : s;
        // gate exchange within warp: lanes q=0 gather f,g,o from lanes +1,+2,+3
        float af = __shfl_down_sync(0xffffffffu, act, 1);
        float ag = __shfl_down_sync(0xffffffffu, act, 2);
        float ao = __shfl_down_sync(0xffffffffu, act, 3);
        if (q == 0) {
            c = af * c + act * ag;               // f*c + i*g
            float hn = ao * tanh_f(c);           // o*tanh(c)
            __half* wbuf = (__half*)(hb + ((m & 1) ^ 1) * 64);
            wbuf[j] = __float2half_rn(hn);       // write buffer (fp16 for next dot)
            d_lstm[(size_t)(m * TT + t) * 128 + j] = hn;
        }
        __syncthreads();
    }
}

// ---------------- fused FC1(relu)+FC2, 64 rows/block, packed f32x2 ----------------
__global__ void __launch_bounds__(256)
k_fc(const float* __restrict__ fc1w, const float* __restrict__ fc1b,
     const float* __restrict__ fc2w, const float* __restrict__ fc2b,
     float* __restrict__ out) {
    extern __shared__ float sm[];
    float* w1t = sm;                   // [64][130]
    float* w2t = w1t + 64 * 130;       // [32][66]
    float* xs  = w2t + 32 * 66;        // [64][128]
    float* mid = xs  + 64 * 128;       // [64][66]
    int tid = threadIdx.x;

    for (int i = tid; i < 128 * 64; i += 256) {
        int k = i >> 6, cc = i & 63;
        w1t[cc * 130 + k] = fc1w[i];
    }
    for (int i = tid; i < 64 * 32; i += 256) {
        int k = i >> 5, o = i & 31;
        w2t[o * 66 + k] = fc2w[i];
    }
    int rbase = blockIdx.x * 64;
    for (int i = tid; i < 64 * 32; i += 256)
        ((float4*)xs)[i] = ((const float4*)d_lstm)[(size_t)rbase * 32 + i];
    __syncthreads();

    int r = tid >> 2, q = tid & 3;
    {
        unsigned long long acc[16];
        #pragma unroll
        for (int j = 0; j < 16; j++) acc[j] = 0ull;
        const unsigned long long* xr = (const unsigned long long*)(xs + r * 128);
        #pragma unroll 4
        for (int kp = 0; kp < 64; kp++) {
            unsigned long long xv = xr[kp];
            #pragma unroll
            for (int j = 0; j < 16; j++)
                FMA2(acc[j], xv, *(const unsigned long long*)(w1t + (q * 16 + j) * 130 + 2 * kp));
        }
        #pragma unroll
        for (int j = 0; j < 16; j++) {
            float lo, hi; UNPK(lo, hi, acc[j]);
            int cc = q * 16 + j;
            mid[r * 66 + cc] = fmaxf(lo + hi + __ldg(&fc1b[cc]), 0.0f);
        }
    }
    __syncthreads();
    {
        unsigned long long acc[8];
        #pragma unroll
        for (int j = 0; j < 8; j++) acc[j] = 0ull;
        const unsigned long long* mr = (const unsigned long long*)(mid + r * 66);
        #pragma unroll 4
        for (int kp = 0; kp < 32; kp++) {
            unsigned long long mv = mr[kp];
            #pragma unroll
            for (int j = 0; j < 8; j++)
                FMA2(acc[j], mv, *(const unsigned long long*)(w2t + (q * 8 + j) * 66 + 2 * kp));
        }
        #pragma unroll
        for (int j = 0; j < 8; j++) {
            float lo, hi; UNPK(lo, hi, acc[j]);
            int o = q * 8 + j;
            out[(size_t)(rbase + r) * 32 + o] = lo + hi + __ldg(&fc2b[o]);
        }
    }
}

// ---------------- launch ----------------
extern "C" void kernel_launch(void* const* d_in, const int* in_sizes, int n_in,
                              void* d_out, int out_size) {
    const float* positions = (const float*)d_in[0];
    const float* adjacency = (const float*)d_in[1];
    const unsigned int* ego = (const unsigned int*)d_in[2];
    const float* W1   = (const float*)d_in[3];
    const float* b1   = (const float*)d_in[4];
    const float* W2   = (const float*)d_in[5];
    const float* b2   = (const float*)d_in[6];
    const float* W_ih = (const float*)d_in[7];
    const float* W_hh = (const float*)d_in[8];
    const float* b_ih = (const float*)d_in[9];
    const float* b_hh = (const float*)d_in[10];
    const float* fc1w = (const float*)d_in[11];
    const float* fc1b = (const float*)d_in[12];
    const float* fc2w = (const float*)d_in[13];
    const float* fc2b = (const float*)d_in[14];
    float* out = (float*)d_out;

    static const int GEMM_SMEM = (64 * 128 + 128 * 130) * 4;            // 99328
    static const int FC_SMEM   = (64 * 130 + 32 * 66 + 64 * 128 + 64 * 66) * 4;  // 91392
    cudaFuncSetAttribute(k_gemm, cudaFuncAttributeMaxDynamicSharedMemorySize, GEMM_SMEM);
    cudaFuncSetAttribute(k_fc,   cudaFuncAttributeMaxDynamicSharedMemorySize, FC_SMEM);

    float* bufA; cudaGetSymbolAddress((void**)&bufA, d_bufA);
    float* bufB; cudaGetSymbolAddress((void**)&bufB, d_bufB);
    float* gpre; cudaGetSymbolAddress((void**)&gpre, d_gpre);

    k_extract<<<dim3(8, TT, NCHUNK), 256>>>(adjacency, ego);
    k_agg1<<<NROWS, 128>>>((const float2*)positions, W1, b1, bufB);
    k_gemm<<<dim3(625, 1), 256, GEMM_SMEM>>>(bufB, W2, bufA, 0, 0, 0, 128);
    k_agg2<<<NROWS, 128>>>(bufA, b2, bufB);
    k_gemm<<<dim3(625, 4), 256, GEMM_SMEM>>>(bufB, W_ih, gpre, b_ih, b_hh, 1, 512);
    k_lstm<<<TT, 512>>>(W_hh);
    k_fc<<<625, 256, FC_SMEM>>>(fc1w, fc1b, fc2w, fc2b, out);
}

// round 16
// speedup vs baseline: 2.7419x; 1.0437x over previous
#include <cuda_runtime.h>
#include <cuda_bf16.h>
#include <cuda_fp16.h>
#include <math.h>

#define TT 20
#define MM 2000
#define NROWS (TT*MM)          // 40000, row index = t*MM + m
#define NCHUNK 4
#define JCH (MM/NCHUNK)        // 500
#define SEG 24                 // per-chunk neighbor capacity
#define CAP (NCHUNK*SEG)       // 96

#define FMA2(d,a,b) asm("fma.rn.f32x2 %0,%1,%2,%0;" : "+l"(d) : "l"(a), "l"(b))
#define UNPK(lo,hi,v) asm("mov.b64 {%0,%1},%2;" : "=f"(lo), "=f"(hi) : "l"(v))

// ---------------- static scratch ----------------
__device__ float          d_maskf[NROWS];
__device__ int            d_cnt4[NCHUNK*NROWS];
__device__ int            d_deg[NROWS];      // zero-init; self-resetting
__device__ int            d_tick[NROWS];     // zero-init; self-resetting
__device__ float          d_dinv[NROWS];
__device__ unsigned short d_nbr[(size_t)NROWS * CAP];
__device__ float          d_bufA[(size_t)NROWS * 128];   // Z2
__device__ float          d_bufB[(size_t)NROWS * 128];   // h1 / placeholder
__device__ float          d_gpre[(size_t)NROWS * 512];   // [m*T+t][512]
__device__ float          d_lstm[(size_t)NROWS * 128];   // [m*T+t][128]

// fast nonlinearities
__device__ __forceinline__ float sigm_f(float x) {
    return __fdividef(1.0f, 1.0f + __expf(-x));
}
__device__ __forceinline__ float tanh_f(float x) {
    return __fdividef(2.0f, 1.0f + __expf(-2.0f * x)) - 1.0f;
}
// single-MUFU tanh (sm_75+): 1 op vs EX2+RCP
__device__ __forceinline__ float tanh_a(float x) {
    float r; asm("tanh.approx.f32 %0, %1;" : "=f"(r) : "f"(x)); return r;
}

// ---------------- chunked extraction + fused degree/dinv (atomic ticket) ----------------
__global__ void k_extract(const float* __restrict__ adj, const unsigned int* __restrict__ em) {
    int t = blockIdx.y;
    int ch = blockIdx.z;
    int j0 = ch * JCH;
    int i = blockIdx.x * 256 + threadIdx.x;
    __shared__ float msm[JCH];
    for (int j = threadIdx.x; j < JCH; j += 256) {
        int gj = j0 + j;
        int b = gj / 500, n = gj % 500;
        msm[j] = em[(b * TT + t) * 500 + n] ? 1.0f : 0.0f;
    }
    __syncthreads();
    if (i >= MM) return;
    const float* a = adj + (size_t)t * MM * MM + (size_t)j0 * MM + i;   // column i, chunk rows
    int idx = t * MM + i;
    unsigned short* list = d_nbr + (size_t)idx * CAP + ch * SEG;
    int cnt = 0;
    #pragma unroll 8
    for (int j = 0; j < JCH; j++) {
        float av = a[(size_t)j * MM];
        if (av != 0.0f && msm[j] != 0.0f) {
            if (cnt < SEG) list[cnt] = (unsigned short)(j0 + j);
            cnt++;
        }
    }
    int cc = (cnt < SEG ? cnt : SEG);
    d_cnt4[ch * NROWS + idx] = cc;
    atomicAdd(&d_deg[idx], cc);
    __threadfence();
    int done = atomicAdd(&d_tick[idx], 1);
    if (done == NCHUNK - 1) {            // last chunk for this column: finalize
        int tot = atomicAdd(&d_deg[idx], 0);
        int b = i / 500, n = i % 500;
        float mi = em[(b * TT + t) * 500 + n] ? 1.0f : 0.0f;
        d_maskf[idx] = mi;
        d_dinv[idx] = (mi != 0.0f) ? rsqrtf((float)tot + 1.0f) : 0.0f;
        d_deg[idx] = 0;                  // self-reset for next graph replay
        d_tick[idx] = 0;
    }
}

// ---------------- fused GCN1: h1 = relu( dinv_i * ((Σ dinv_j x_j) @ W1) + b1 ) ----------------
__global__ void k_agg1(const float2* __restrict__ pos2, const float* __restrict__ W1,
                       const float* __restrict__ b1, float* __restrict__ out) {
    int row = blockIdx.x;
    int f = threadIdx.x;
    int t = row / MM;
    size_t base = (size_t)t * MM;
    float di = d_dinv[row];
    float2 xi = __ldg(&pos2[row]);
    float wx0 = di * xi.x, wx1 = di * xi.y;      // self term
    const unsigned short* lrow = &d_nbr[(size_t)row * CAP];
    #pragma unroll
    for (int ch = 0; ch < NCHUNK; ch++) {
        int n = d_cnt4[ch * NROWS + row];
        const unsigned short* lst = lrow + ch * SEG;
        for (int idx = 0; idx < n; idx++) {
            size_t j = base + lst[idx];
            float dj = __ldg(&d_dinv[j]);
            float2 xj = __ldg(&pos2[j]);
            wx0 += dj * xj.x;
            wx1 += dj * xj.y;
        }
    }
    float v = di * (wx0 * __ldg(&W1[f]) + wx1 * __ldg(&W1[128 + f])) + __ldg(&b1[f]);
    out[(size_t)row * 128 + f] = fmaxf(v, 0.0f);
}

// ---------------- GCN2 aggregation: out = (dinv_i*(Σ Z2[j] + Z2[i]) + b2) * mask ----------------
__global__ void k_agg2(const float* __restrict__ Zin, const float* __restrict__ bias,
                       float* __restrict__ out) {
    int row = blockIdx.x;
    int f = threadIdx.x;
    int t = row / MM;
    size_t base = (size_t)t * MM;
    float acc = Zin[(size_t)row * 128 + f];
    const unsigned short* lrow = &d_nbr[(size_t)row * CAP];
    #pragma unroll
    for (int ch = 0; ch < NCHUNK; ch++) {
        int n = d_cnt4[ch * NROWS + row];
        const unsigned short* lst = lrow + ch * SEG;
        for (int idx = 0; idx < n; idx++) {
            int j = lst[idx];
            acc += Zin[(base + j) * 128 + f];
        }
    }
    float v = d_dinv[row] * acc + __ldg(&bias[f]);
    out[(size_t)row * 128 + f] = v * d_maskf[row];
}

// ---------------- tiled GEMM, K=128 fixed, packed f32x2 (proven R14 version) ----------------
// mode 0 (Z2):    A row = r,                B = W2   [k][c],  epi: *dinv[r]
// mode 1 (gates): A row = (r%20)*2000+r/20, B = W_ih [c][k],  epi: + b_ih[c]+b_hh[c]
__global__ void __launch_bounds__(256)
k_gemm(const float* __restrict__ A, const float* __restrict__ B, float* __restrict__ C,
       const float* __restrict__ bia, const float* __restrict__ bib,
       int mode, int ncols) {
    extern __shared__ float sm[];
    float* As = sm;            // [64][128]
    float* Bs = sm + 64 * 128; // [128][130]
    int r0 = blockIdx.x * 64, c0 = blockIdx.y * 128;
    int tid = threadIdx.x;

    for (int i = tid; i < 64 * 32; i += 256) {
        int row = i / 32, k4 = i % 32;
        int gr = r0 + row;
        int arow = (mode == 1) ? ((gr % TT) * MM + gr / TT) : gr;
        ((float4*)As)[row * 32 + k4] = ((const float4*)A)[(size_t)arow * 32 + k4];
    }
    if (mode == 1) {
        for (int i = tid; i < 128 * 32; i += 256) {
            int c = i / 32, k4 = i % 32;
            float4 v = ((const float4*)B)[(size_t)(c0 + c) * 32 + k4];
            Bs[c * 130 + 4 * k4 + 0] = v.x; Bs[c * 130 + 4 * k4 + 1] = v.y;
            Bs[c * 130 + 4 * k4 + 2] = v.z; Bs[c * 130 + 4 * k4 + 3] = v.w;
        }
    } else {
        for (int i = tid; i < 128 * 32; i += 256) {
            int k = i / 32, c4 = i % 32;
            float4 v = ((const float4*)B)[(size_t)k * 32 + c4];
            Bs[(4 * c4 + 0) * 130 + k] = v.x; Bs[(4 * c4 + 1) * 130 + k] = v.y;
            Bs[(4 * c4 + 2) * 130 + k] = v.z; Bs[(4 * c4 + 3) * 130 + k] = v.w;
        }
    }
    __syncthreads();

    int tx = tid % 32, ty = tid / 32;
    unsigned long long acc[8][4];
    #pragma unroll
    for (int rr = 0; rr < 8; rr++)
        #pragma unroll
        for (int cc = 0; cc < 4; cc++) acc[rr][cc] = 0ull;

    const ulonglong2* As2 = (const ulonglong2*)As;
    #pragma unroll 4
    for (int k4 = 0; k4 < 32; k4++) {
        ulonglong2 a[8];
        #pragma unroll
        for (int rr = 0; rr < 8; rr++) a[rr] = As2[(ty * 8 + rr) * 32 + k4];
        #pragma unroll
        for (int cc = 0; cc < 4; cc++) {
            int c = tx + 32 * cc;
            const unsigned long long* bp = (const unsigned long long*)(Bs + c * 130 + 4 * k4);
            unsigned long long b0 = bp[0], b1 = bp[1];
            #pragma unroll
            for (int rr = 0; rr < 8; rr++) {
                FMA2(acc[rr][cc], a[rr].x, b0);
                FMA2(acc[rr][cc], a[rr].y, b1);
            }
        }
    }
    #pragma unroll
    for (int cc = 0; cc < 4; cc++) {
        int c = tx + 32 * cc;
        float bv = (mode == 1) ? (__ldg(&bia[c0 + c]) + __ldg(&bib[c0 + c])) : 0.0f;
        #pragma unroll
        for (int rr = 0; rr < 8; rr++) {
            int r = r0 + ty * 8 + rr;
            float lo, hi; UNPK(lo, hi, acc[rr][cc]);
            float v = lo + hi;
            if (mode == 1) v += bv;
            else           v *= d_dinv[r];
            C[(size_t)r * ncols + c0 + c] = v;
        }
    }
}

// ---------------- persistent LSTM: 20 blocks, 512 threads, fp16 HFMA2 + 4-deep gpre prefetch ----------------
// Thread g -> gate row grow=q*128+j. ALL 128 weights in 64 half2 regs (fp16);
// h stored in smem as half2, double-buffered. Dot = 64 HFMA2 over 4 chains,
// combined fp32. Nonlinearities via single-MUFU tanh.approx:
//   tanh(x) directly; sigm(x) = 0.5*tanh(x/2)+0.5 (branchless across quad).
// gpre prefetched 4 steps ahead. Shuffle gate exchange, 1 bar/step.
__global__ void __launch_bounds__(512, 1)
k_lstm(const float* __restrict__ Whh) {
    __shared__ __align__(16) unsigned hb[128];   // [2][64] u32 = half2 h, double-buffered
    int t = blockIdx.x, g = threadIdx.x;
    int q = g & 3, j = g >> 2;
    int grow = q * 128 + j;                      // gate row in [512]

    __half2 wh[64];
    const float2* wrow = (const float2*)(Whh + (size_t)grow * 128);
    #pragma unroll
    for (int i = 0; i < 64; i++) wh[i] = __float22half2_rn(wrow[i]);

    float c = 0.0f;
    if (g < 128) hb[g] = 0u;                     // zero both buffers
    __syncthreads();

    // 4-deep gpre prefetch ring: gp0 = step m, ng1..ng3 = m+1..m+3 in flight
    float gp0 = d_gpre[(size_t)(0 * TT + t) * 512 + grow];
    float ng1 = d_gpre[(size_t)(1 * TT + t) * 512 + grow];
    float ng2 = d_gpre[(size_t)(2 * TT + t) * 512 + grow];
    float ng3 = d_gpre[(size_t)(3 * TT + t) * 512 + grow];

    // branchless nonlinearity constants per quad: act = s*tanh(k*x) + b
    float kin = (q == 2) ? 1.0f : 0.5f;          // tanh input scale
    float sct = (q == 2) ? 1.0f : 0.5f;          // output scale
    float bct = (q == 2) ? 0.0f : 0.5f;          // output bias

    for (int m = 0; m < MM; m++) {
        float gp = gp0;
        gp0 = ng1; ng1 = ng2; ng2 = ng3;
        if (m + 4 < MM) ng3 = d_gpre[(size_t)((m + 4) * TT + t) * 512 + grow];
        const uint4* h4 = (const uint4*)(hb + (m & 1) * 64);
        __half2 a0 = __float2half2_rn(0.0f), a1 = a0, a2 = a0, a3 = a0;
        #pragma unroll
        for (int i = 0; i < 16; i++) {           // 64 HFMA2 over 4 chains
            uint4 hv = h4[i];
            a0 = __hfma2(*(__half2*)&hv.x, wh[4 * i + 0], a0);
            a1 = __hfma2(*(__half2*)&hv.y, wh[4 * i + 1], a1);
            a2 = __hfma2(*(__half2*)&hv.z, wh[4 * i + 2], a2);
            a3 = __hfma2(*(__half2*)&hv.w, wh[4 * i + 3], a3);
        }
        float part = (__low2float(a0) + __high2float(a0))
                   + (__low2float(a1) + __high2float(a1))
                   + (__low2float(a2) + __high2float(a2))
                   + (__low2float(a3) + __high2float(a3)) + gp;
        // single-MUFU nonlinearity: tanh for q==2, sigmoid (=0.5*tanh(x/2)+0.5) otherwise
        float act = fmaf(sct, tanh_a(kin * part), bct);
        // gate exchange within warp: lanes q=0 gather f,g,o from lanes +1,+2,+3
        float af = __shfl_down_sync(0xffffffffu, act, 1);
        float ag = __shfl_down_sync(0xffffffffu, act, 2);
        float ao = __shfl_down_sync(0xffffffffu, act, 3);
        if (q == 0) {
            c = af * c + act * ag;               // f*c + i*g
            float hn = ao * tanh_a(c);           // o*tanh(c), single MUFU
            __half* wbuf = (__half*)(hb + ((m & 1) ^ 1) * 64);
            wbuf[j] = __float2half_rn(hn);       // write buffer (fp16 for next dot)
            d_lstm[(size_t)(m * TT + t) * 128 + j] = hn;
        }
        __syncthreads();
    }
}

// ---------------- fused FC1(relu)+FC2, 64 rows/block, packed f32x2 ----------------
__global__ void __launch_bounds__(256)
k_fc(const float* __restrict__ fc1w, const float* __restrict__ fc1b,
     const float* __restrict__ fc2w, const float* __restrict__ fc2b,
     float* __restrict__ out) {
    extern __shared__ float sm[];
    float* w1t = sm;                   // [64][130]
    float* w2t = w1t + 64 * 130;       // [32][66]
    float* xs  = w2t + 32 * 66;        // [64][128]
    float* mid = xs  + 64 * 128;       // [64][66]
    int tid = threadIdx.x;

    for (int i = tid; i < 128 * 64; i += 256) {
        int k = i >> 6, cc = i & 63;
        w1t[cc * 130 + k] = fc1w[i];
    }
    for (int i = tid; i < 64 * 32; i += 256) {
        int k = i >> 5, o = i & 31;
        w2t[o * 66 + k] = fc2w[i];
    }
    int rbase = blockIdx.x * 64;
    for (int i = tid; i < 64 * 32; i += 256)
        ((float4*)xs)[i] = ((const float4*)d_lstm)[(size_t)rbase * 32 + i];
    __syncthreads();

    int r = tid >> 2, q = tid & 3;
    {
        unsigned long long acc[16];
        #pragma unroll
        for (int j = 0; j < 16; j++) acc[j] = 0ull;
        const unsigned long long* xr = (const unsigned long long*)(xs + r * 128);
        #pragma unroll 4
        for (int kp = 0; kp < 64; kp++) {
            unsigned long long xv = xr[kp];
            #pragma unroll
            for (int j = 0; j < 16; j++)
                FMA2(acc[j], xv, *(const unsigned long long*)(w1t + (q * 16 + j) * 130 + 2 * kp));
        }
        #pragma unroll
        for (int j = 0; j < 16; j++) {
            float lo, hi; UNPK(lo, hi, acc[j]);
            int cc = q * 16 + j;
            mid[r * 66 + cc] = fmaxf(lo + hi + __ldg(&fc1b[cc]), 0.0f);
        }
    }
    __syncthreads();
    {
        unsigned long long acc[8];
        #pragma unroll
        for (int j = 0; j < 8; j++) acc[j] = 0ull;
        const unsigned long long* mr = (const unsigned long long*)(mid + r * 66);
        #pragma unroll 4
        for (int kp = 0; kp < 32; kp++) {
            unsigned long long mv = mr[kp];
            #pragma unroll
            for (int j = 0; j < 8; j++)
                FMA2(acc[j], mv, *(const unsigned long long*)(w2t + (q * 8 + j) * 66 + 2 * kp));
        }
        #pragma unroll
        for (int j = 0; j < 8; j++) {
            float lo, hi; UNPK(lo, hi, acc[j]);
            int o = q * 8 + j;
            out[(size_t)(rbase + r) * 32 + o] = lo + hi + __ldg(&fc2b[o]);
        }
    }
}

// ---------------- launch ----------------
extern "C" void kernel_launch(void* const* d_in, const int* in_sizes, int n_in,
                              void* d_out, int out_size) {
    const float* positions = (const float*)d_in[0];
    const float* adjacency = (const float*)d_in[1];
    const unsigned int* ego = (const unsigned int*)d_in[2];
    const float* W1   = (const float*)d_in[3];
    const float* b1   = (const float*)d_in[4];
    const float* W2   = (const float*)d_in[5];
    const float* b2   = (const float*)d_in[6];
    const float* W_ih = (const float*)d_in[7];
    const float* W_hh = (const float*)d_in[8];
    const float* b_ih = (const float*)d_in[9];
    const float* b_hh = (const float*)d_in[10];
    const float* fc1w = (const float*)d_in[11];
    const float* fc1b = (const float*)d_in[12];
    const float* fc2w = (const float*)d_in[13];
    const float* fc2b = (const float*)d_in[14];
    float* out = (float*)d_out;

    static const int GEMM_SMEM = (64 * 128 + 128 * 130) * 4;            // 99328
    static const int FC_SMEM   = (64 * 130 + 32 * 66 + 64 * 128 + 64 * 66) * 4;  // 91392
    cudaFuncSetAttribute(k_gemm, cudaFuncAttributeMaxDynamicSharedMemorySize, GEMM_SMEM);
    cudaFuncSetAttribute(k_fc,   cudaFuncAttributeMaxDynamicSharedMemorySize, FC_SMEM);

    float* bufA; cudaGetSymbolAddress((void**)&bufA, d_bufA);
    float* bufB; cudaGetSymbolAddress((void**)&bufB, d_bufB);
    float* gpre; cudaGetSymbolAddress((void**)&gpre, d_gpre);

    k_extract<<<dim3(8, TT, NCHUNK), 256>>>(adjacency, ego);
    k_agg1<<<NROWS, 128>>>((const float2*)positions, W1, b1, bufB);
    k_gemm<<<dim3(625, 1), 256, GEMM_SMEM>>>(bufB, W2, bufA, 0, 0, 0, 128);
    k_agg2<<<NROWS, 128>>>(bufA, b2, bufB);
    k_gemm<<<dim3(625, 4), 256, GEMM_SMEM>>>(bufB, W_ih, gpre, b_ih, b_hh, 1, 512);
    k_lstm<<<TT, 512>>>(W_hh);
    k_fc<<<625, 256, FC_SMEM>>>(fc1w, fc1b, fc2w, fc2b, out);
}

// round 17
// speedup vs baseline: 2.8676x; 1.0458x over previous
#include <cuda_runtime.h>
#include <cuda_bf16.h>
#include <cuda_fp16.h>
#include <math.h>

#define TT 20
#define MM 2000
#define NROWS (TT*MM)          // 40000, row index = t*MM + m
#define NCHUNK 4
#define JCH (MM/NCHUNK)        // 500
#define SEG 24                 // per-chunk neighbor capacity
#define CAP (NCHUNK*SEG)       // 96

#define FMA2(d,a,b) asm("fma.rn.f32x2 %0,%1,%2,%0;" : "+l"(d) : "l"(a), "l"(b))
#define UNPK(lo,hi,v) asm("mov.b64 {%0,%1},%2;" : "=f"(lo), "=f"(hi) : "l"(v))

// ---------------- static scratch ----------------
__device__ float          d_maskf[NROWS];
__device__ int            d_cnt4[NCHUNK*NROWS];
__device__ int            d_deg[NROWS];      // zero-init; self-resetting
__device__ int            d_tick[NROWS];     // zero-init; self-resetting
__device__ float          d_dinv[NROWS];
__device__ unsigned short d_nbr[(size_t)NROWS * CAP];
__device__ float          d_bufA[(size_t)NROWS * 128];   // Z2             [t*MM+m]
__device__ float          d_bufB[(size_t)NROWS * 128];   // h1 [t*MM+m] / placeholder [m*TT+t]
__device__ float          d_gpre[(size_t)NROWS * 512];   // [m*TT+t][512]
__device__ float          d_lstm[(size_t)NROWS * 128];   // [m*TT+t][128]

// fast nonlinearities
__device__ __forceinline__ float sigm_f(float x) {
    return __fdividef(1.0f, 1.0f + __expf(-x));
}
// single-MUFU tanh (sm_75+)
__device__ __forceinline__ float tanh_a(float x) {
    float r; asm("tanh.approx.f32 %0, %1;" : "=f"(r) : "f"(x)); return r;
}

// ---------------- chunked extraction + fused degree/dinv (atomic ticket) ----------------
__global__ void k_extract(const float* __restrict__ adj, const unsigned int* __restrict__ em) {
    int t = blockIdx.y;
    int ch = blockIdx.z;
    int j0 = ch * JCH;
    int i = blockIdx.x * 256 + threadIdx.x;
    __shared__ float msm[JCH];
    for (int j = threadIdx.x; j < JCH; j += 256) {
        int gj = j0 + j;
        int b = gj / 500, n = gj % 500;
        msm[j] = em[(b * TT + t) * 500 + n] ? 1.0f : 0.0f;
    }
    __syncthreads();
    if (i >= MM) return;
    const float* a = adj + (size_t)t * MM * MM + (size_t)j0 * MM + i;   // column i, chunk rows
    int idx = t * MM + i;
    unsigned short* list = d_nbr + (size_t)idx * CAP + ch * SEG;
    int cnt = 0;
    #pragma unroll 8
    for (int j = 0; j < JCH; j++) {
        float av = a[(size_t)j * MM];
        if (av != 0.0f && msm[j] != 0.0f) {
            if (cnt < SEG) list[cnt] = (unsigned short)(j0 + j);
            cnt++;
        }
    }
    int cc = (cnt < SEG ? cnt : SEG);
    d_cnt4[ch * NROWS + idx] = cc;
    atomicAdd(&d_deg[idx], cc);
    __threadfence();
    int done = atomicAdd(&d_tick[idx], 1);
    if (done == NCHUNK - 1) {            // last chunk for this column: finalize
        int tot = atomicAdd(&d_deg[idx], 0);
        int b = i / 500, n = i % 500;
        float mi = em[(b * TT + t) * 500 + n] ? 1.0f : 0.0f;
        d_maskf[idx] = mi;
        d_dinv[idx] = (mi != 0.0f) ? rsqrtf((float)tot + 1.0f) : 0.0f;
        d_deg[idx] = 0;                  // self-reset for next graph replay
        d_tick[idx] = 0;
    }
}

// ---------------- fused GCN1: h1 = relu( dinv_i * ((Σ dinv_j x_j) @ W1) + b1 ) ----------------
__global__ void k_agg1(const float2* __restrict__ pos2, const float* __restrict__ W1,
                       const float* __restrict__ b1, float* __restrict__ out) {
    int row = blockIdx.x;
    int f = threadIdx.x;
    int t = row / MM;
    size_t base = (size_t)t * MM;
    float di = d_dinv[row];
    float2 xi = __ldg(&pos2[row]);
    float wx0 = di * xi.x, wx1 = di * xi.y;      // self term
    const unsigned short* lrow = &d_nbr[(size_t)row * CAP];
    #pragma unroll
    for (int ch = 0; ch < NCHUNK; ch++) {
        int n = d_cnt4[ch * NROWS + row];
        const unsigned short* lst = lrow + ch * SEG;
        for (int idx = 0; idx < n; idx++) {
            size_t j = base + lst[idx];
            float dj = __ldg(&d_dinv[j]);
            float2 xj = __ldg(&pos2[j]);
            wx0 += dj * xj.x;
            wx1 += dj * xj.y;
        }
    }
    float v = di * (wx0 * __ldg(&W1[f]) + wx1 * __ldg(&W1[128 + f])) + __ldg(&b1[f]);
    out[(size_t)row * 128 + f] = fmaxf(v, 0.0f);
}

// ---------------- GCN2 aggregation: out = (dinv_i*(Σ Z2[j] + Z2[i]) + b2) * mask ----------------
// Output written in LSTM order [(m*TT+t)*128] so downstream GEMM A-loads are coalesced.
__global__ void k_agg2(const float* __restrict__ Zin, const float* __restrict__ bias,
                       float* __restrict__ out) {
    int row = blockIdx.x;                // row = t*MM + m
    int f = threadIdx.x;
    int t = row / MM;
    int m = row - t * MM;
    size_t base = (size_t)t * MM;
    float acc = Zin[(size_t)row * 128 + f];
    const unsigned short* lrow = &d_nbr[(size_t)row * CAP];
    #pragma unroll
    for (int ch = 0; ch < NCHUNK; ch++) {
        int n = d_cnt4[ch * NROWS + row];
        const unsigned short* lst = lrow + ch * SEG;
        for (int idx = 0; idx < n; idx++) {
            int j = lst[idx];
            acc += Zin[(base + j) * 128 + f];
        }
    }
    float v = d_dinv[row] * acc + __ldg(&bias[f]);
    out[(size_t)(m * TT + t) * 128 + f] = v * d_maskf[row];
}

// ---------------- tiled GEMM, K=128 fixed, packed f32x2, coalesced A for both modes ----------------
// mode 0 (Z2):    B = W2   [k][c],  epi: *dinv[r]      (A,C in [t*MM+m] order)
// mode 1 (gates): B = W_ih [c][k],  epi: + b_ih+b_hh   (A,C in [m*TT+t] order)
__global__ void __launch_bounds__(256)
k_gemm(const float* __restrict__ A, const float* __restrict__ B, float* __restrict__ C,
       const float* __restrict__ bia, const float* __restrict__ bib,
       int mode, int ncols) {
    extern __shared__ float sm[];
    float* As = sm;            // [64][128]
    float* Bs = sm + 64 * 128; // [128][130]
    int r0 = blockIdx.x * 64, c0 = blockIdx.y * 128;
    int tid = threadIdx.x;

    for (int i = tid; i < 64 * 32; i += 256) {
        int row = i / 32, k4 = i % 32;
        ((float4*)As)[row * 32 + k4] = ((const float4*)A)[(size_t)(r0 + row) * 32 + k4];
    }
    if (mode == 1) {
        for (int i = tid; i < 128 * 32; i += 256) {
            int c = i / 32, k4 = i % 32;
            float4 v = ((const float4*)B)[(size_t)(c0 + c) * 32 + k4];
            Bs[c * 130 + 4 * k4 + 0] = v.x; Bs[c * 130 + 4 * k4 + 1] = v.y;
            Bs[c * 130 + 4 * k4 + 2] = v.z; Bs[c * 130 + 4 * k4 + 3] = v.w;
        }
    } else {
        for (int i = tid; i < 128 * 32; i += 256) {
            int k = i / 32, c4 = i % 32;
            float4 v = ((const float4*)B)[(size_t)k * 32 + c4];
            Bs[(4 * c4 + 0) * 130 + k] = v.x; Bs[(4 * c4 + 1) * 130 + k] = v.y;
            Bs[(4 * c4 + 2) * 130 + k] = v.z; Bs[(4 * c4 + 3) * 130 + k] = v.w;
        }
    }
    __syncthreads();

    int tx = tid % 32, ty = tid / 32;
    unsigned long long acc[8][4];
    #pragma unroll
    for (int rr = 0; rr < 8; rr++)
        #pragma unroll
        for (int cc = 0; cc < 4; cc++) acc[rr][cc] = 0ull;

    const ulonglong2* As2 = (const ulonglong2*)As;
    #pragma unroll 4
    for (int k4 = 0; k4 < 32; k4++) {
        ulonglong2 a[8];
        #pragma unroll
        for (int rr = 0; rr < 8; rr++) a[rr] = As2[(ty * 8 + rr) * 32 + k4];
        #pragma unroll
        for (int cc = 0; cc < 4; cc++) {
            int c = tx + 32 * cc;
            const unsigned long long* bp = (const unsigned long long*)(Bs + c * 130 + 4 * k4);
            unsigned long long b0 = bp[0], b1 = bp[1];
            #pragma unroll
            for (int rr = 0; rr < 8; rr++) {
                FMA2(acc[rr][cc], a[rr].x, b0);
                FMA2(acc[rr][cc], a[rr].y, b1);
            }
        }
    }
    #pragma unroll
    for (int cc = 0; cc < 4; cc++) {
        int c = tx + 32 * cc;
        float bv = (mode == 1) ? (__ldg(&bia[c0 + c]) + __ldg(&bib[c0 + c])) : 0.0f;
        #pragma unroll
        for (int rr = 0; rr < 8; rr++) {
            int r = r0 + ty * 8 + rr;
            float lo, hi; UNPK(lo, hi, acc[rr][cc]);
            float v = lo + hi;
            if (mode == 1) v += bv;
            else           v *= d_dinv[r];
            C[(size_t)r * ncols + c0 + c] = v;
        }
    }
}

// ---------------- persistent LSTM: 20 blocks, 512 threads, fp16 HFMA2 ----------------
// Thread g -> gate row grow=q*128+j; 64 half2 weight regs; h double-buffered half2
// in smem; single-MUFU tanh.approx nonlinearities; m-loop unrolled x2 (static
// buffer indices); gpre/d_lstm via running pointers (no per-step index mul).
__global__ void __launch_bounds__(512, 1)
k_lstm(const float* __restrict__ Whh) {
    __shared__ __align__(16) unsigned hb[128];   // [2][64] u32 = half2 h
    int t = blockIdx.x, g = threadIdx.x;
    int q = g & 3, j = g >> 2;
    int grow = q * 128 + j;                      // gate row in [512]

    __half2 wh[64];
    const float2* wrow = (const float2*)(Whh + (size_t)grow * 128);
    #pragma unroll
    for (int i = 0; i < 64; i++) wh[i] = __float22half2_rn(wrow[i]);

    float c = 0.0f;
    if (g < 128) hb[g] = 0u;                     // zero both buffers
    __syncthreads();

    const size_t GS = (size_t)TT * 512;          // gpre stride per m
    const float* gp_base = d_gpre + (size_t)t * 512 + grow;
    const float* gend = d_gpre + GS * MM;
    float gp0 = gp_base[0];
    float ng1 = gp_base[GS];
    float ng2 = gp_base[2 * GS];
    float ng3 = gp_base[3 * GS];
    const float* gpf = gp_base + 4 * GS;         // m+4 prefetch pointer
    float* lp = d_lstm + (size_t)t * 128 + j;    // h output pointer (q0 lanes)

    // branchless nonlinearity constants per quad: act = s*tanh(k*x) + b
    float kin = (q == 2) ? 1.0f : 0.5f;
    float sct = (q == 2) ? 1.0f : 0.5f;
    float bct = (q == 2) ? 0.0f : 0.5f;

    #define LSTM_STEP(RB, WB) do {                                             \
        float gp = gp0;                                                        \
        gp0 = ng1; ng1 = ng2; ng2 = ng3;                                       \
        if (gpf < gend) ng3 = *gpf;                                            \
        gpf += GS;                                                             \
        const uint4* h4 = (const uint4*)(hb + (RB));                           \
        __half2 a0 = __float2half2_rn(0.0f), a1 = a0, a2 = a0, a3 = a0;        \
        _Pragma("unroll")                                                      \
        for (int i = 0; i < 16; i++) {                                         \
            uint4 hv = h4[i];                                                  \
            a0 = __hfma2(*(__half2*)&hv.x, wh[4 * i + 0], a0);                 \
            a1 = __hfma2(*(__half2*)&hv.y, wh[4 * i + 1], a1);                 \
            a2 = __hfma2(*(__half2*)&hv.z, wh[4 * i + 2], a2);                 \
            a3 = __hfma2(*(__half2*)&hv.w, wh[4 * i + 3], a3);                 \
        }                                                                      \
        float part = (__low2float(a0) + __high2float(a0))                      \
                   + (__low2float(a1) + __high2float(a1))                      \
                   + (__low2float(a2) + __high2float(a2))                      \
                   + (__low2float(a3) + __high2float(a3)) + gp;                \
        float act = fmaf(sct, tanh_a(kin * part), bct);                        \
        float af = __shfl_down_sync(0xffffffffu, act, 1);                      \
        float ag = __shfl_down_sync(0xffffffffu, act, 2);                      \
        float ao = __shfl_down_sync(0xffffffffu, act, 3);                      \
        if (q == 0) {                                                          \
            c = af * c + act * ag;                                             \
            float hn = ao * tanh_a(c);                                         \
            ((__half*)(hb + (WB)))[j] = __float2half_rn(hn);                   \
            *lp = hn;                                                          \
        }                                                                      \
        lp += TT * 128;                                                        \
        __syncthreads();                                                       \
    } while (0)

    #pragma unroll 1
    for (int m = 0; m < MM; m += 2) {
        LSTM_STEP(0, 64);     // even step: read buf0, write buf1
        LSTM_STEP(64, 0);     // odd  step: read buf1, write buf0
    }
    #undef LSTM_STEP
}

// ---------------- fused FC1(relu)+FC2, 64 rows/block, packed f32x2 ----------------
__global__ void __launch_bounds__(256)
k_fc(const float* __restrict__ fc1w, const float* __restrict__ fc1b,
     const float* __restrict__ fc2w, const float* __restrict__ fc2b,
     float* __restrict__ out) {
    extern __shared__ float sm[];
    float* w1t = sm;                   // [64][130]
    float* w2t = w1t + 64 * 130;       // [32][66]
    float* xs  = w2t + 32 * 66;        // [64][128]
    float* mid = xs  + 64 * 128;       // [64][66]
    int tid = threadIdx.x;

    for (int i = tid; i < 128 * 64; i += 256) {
        int k = i >> 6, cc = i & 63;
        w1t[cc * 130 + k] = fc1w[i];
    }
    for (int i = tid; i < 64 * 32; i += 256) {
        int k = i >> 5, o = i & 31;
        w2t[o * 66 + k] = fc2w[i];
    }
    int rbase = blockIdx.x * 64;
    for (int i = tid; i < 64 * 32; i += 256)
        ((float4*)xs)[i] = ((const float4*)d_lstm)[(size_t)rbase * 32 + i];
    __syncthreads();

    int r = tid >> 2, q = tid & 3;
    {
        unsigned long long acc[16];
        #pragma unroll
        for (int j = 0; j < 16; j++) acc[j] = 0ull;
        const unsigned long long* xr = (const unsigned long long*)(xs + r * 128);
        #pragma unroll 4
        for (int kp = 0; kp < 64; kp++) {
            unsigned long long xv = xr[kp];
            #pragma unroll
            for (int j = 0; j < 16; j++)
                FMA2(acc[j], xv, *(const unsigned long long*)(w1t + (q * 16 + j) * 130 + 2 * kp));
        }
        #pragma unroll
        for (int j = 0; j < 16; j++) {
            float lo, hi; UNPK(lo, hi, acc[j]);
            int cc = q * 16 + j;
            mid[r * 66 + cc] = fmaxf(lo + hi + __ldg(&fc1b[cc]), 0.0f);
        }
    }
    __syncthreads();
    {
        unsigned long long acc[8];
        #pragma unroll
        for (int j = 0; j < 8; j++) acc[j] = 0ull;
        const unsigned long long* mr = (const unsigned long long*)(mid + r * 66);
        #pragma unroll 4
        for (int kp = 0; kp < 32; kp++) {
            unsigned long long mv = mr[kp];
            #pragma unroll
            for (int j = 0; j < 8; j++)
                FMA2(acc[j], mv, *(const unsigned long long*)(w2t + (q * 8 + j) * 66 + 2 * kp));
        }
        #pragma unroll
        for (int j = 0; j < 8; j++) {
            float lo, hi; UNPK(lo, hi, acc[j]);
            int o = q * 8 + j;
            out[(size_t)(rbase + r) * 32 + o] = lo + hi + __ldg(&fc2b[o]);
        }
    }
}

// ---------------- launch ----------------
extern "C" void kernel_launch(void* const* d_in, const int* in_sizes, int n_in,
                              void* d_out, int out_size) {
    const float* positions = (const float*)d_in[0];
    const float* adjacency = (const float*)d_in[1];
    const unsigned int* ego = (const unsigned int*)d_in[2];
    const float* W1   = (const float*)d_in[3];
    const float* b1   = (const float*)d_in[4];
    const float* W2   = (const float*)d_in[5];
    const float* b2   = (const float*)d_in[6];
    const float* W_ih = (const float*)d_in[7];
    const float* W_hh = (const float*)d_in[8];
    const float* b_ih = (const float*)d_in[9];
    const float* b_hh = (const float*)d_in[10];
    const float* fc1w = (const float*)d_in[11];
    const float* fc1b = (const float*)d_in[12];
    const float* fc2w = (const float*)d_in[13];
    const float* fc2b = (const float*)d_in[14];
    float* out = (float*)d_out;

    static const int GEMM_SMEM = (64 * 128 + 128 * 130) * 4;            // 99328
    static const int FC_SMEM   = (64 * 130 + 32 * 66 + 64 * 128 + 64 * 66) * 4;  // 91392
    cudaFuncSetAttribute(k_gemm, cudaFuncAttributeMaxDynamicSharedMemorySize, GEMM_SMEM);
    cudaFuncSetAttribute(k_fc,   cudaFuncAttributeMaxDynamicSharedMemorySize, FC_SMEM);

    float* bufA; cudaGetSymbolAddress((void**)&bufA, d_bufA);
    float* bufB; cudaGetSymbolAddress((void**)&bufB, d_bufB);
    float* gpre; cudaGetSymbolAddress((void**)&gpre, d_gpre);

    k_extract<<<dim3(8, TT, NCHUNK), 256>>>(adjacency, ego);
    k_agg1<<<NROWS, 128>>>((const float2*)positions, W1, b1, bufB);
    k_gemm<<<dim3(625, 1), 256, GEMM_SMEM>>>(bufB, W2, bufA, 0, 0, 0, 128);
    k_agg2<<<NROWS, 128>>>(bufA, b2, bufB);          // writes [m*TT+t] order
    k_gemm<<<dim3(625, 4), 256, GEMM_SMEM>>>(bufB, W_ih, gpre, b_ih, b_hh, 1, 512);
    k_lstm<<<TT, 512>>>(W_hh);
    k_fc<<<625, 256, FC_SMEM>>>(fc1w, fc1b, fc2w, fc2b, out);
}